// round 1
// baseline (speedup 1.0000x reference)
#include <cuda_runtime.h>

// Problem constants
#define BB   4
#define SS   1024
#define DIN  768
#define HH   12
#define DH   64
#define BM   64      // row tile
#define BK   32      // k chunk for projection

// Scratch for projected Q/K/V in [b,h,s,e] layout (device globals: no allocs allowed)
__device__ float g_Q[BB*HH*SS*DH];
__device__ float g_K[BB*HH*SS*DH];
__device__ float g_V[BB*HH*SS*DH];

// ---------------------------------------------------------------------------
// Kernel 1: fused QKV projection.
// grid (S/64, H, B), 256 threads. Each block computes 64x64 tiles of Q,K,V for
// one head: one x-tile load feeds all three weight tiles.
// ---------------------------------------------------------------------------
__global__ __launch_bounds__(256, 2)
void qkv_proj_kernel(const float* __restrict__ x,
                     const float* __restrict__ Wq,
                     const float* __restrict__ Wk,
                     const float* __restrict__ Wv) {
    __shared__ float Xs [BK][BM+4];   // [k][row]  (transposed for float4 reads)
    __shared__ float Bqs[BK][BM+4];   // [k][col]
    __shared__ float Bks[BK][BM+4];
    __shared__ float Bvs[BK][BM+4];

    const int mt = blockIdx.x, h = blockIdx.y, b = blockIdx.z;
    const int tid = threadIdx.x;
    const int tx = tid & 15, ty = tid >> 4;
    const int m0 = mt * BM;

    float aq[4][4] = {}, ak[4][4] = {}, av[4][4] = {};

    const float* xb = x  + ((size_t)b*SS + m0) * DIN;
    const float* wq = Wq + (size_t)h * DIN * DH;
    const float* wk = Wk + (size_t)h * DIN * DH;
    const float* wv = Wv + (size_t)h * DIN * DH;

    for (int k0 = 0; k0 < DIN; k0 += BK) {
        // X tile: 64 rows x 32 k, stored transposed Xs[k][row]
        #pragma unroll
        for (int u = 0; u < 8; u++) {
            int idx = tid + u*256;          // 0..2047
            int row = idx >> 5, kk = idx & 31;
            Xs[kk][row] = xb[(size_t)row*DIN + k0 + kk];
        }
        // W tiles: 32 k x 64 col
        #pragma unroll
        for (int u = 0; u < 8; u++) {
            int idx = tid + u*256;
            int kk = idx >> 6, col = idx & 63;
            size_t off = (size_t)(k0+kk)*DH + col;
            Bqs[kk][col] = wq[off];
            Bks[kk][col] = wk[off];
            Bvs[kk][col] = wv[off];
        }
        __syncthreads();

        #pragma unroll
        for (int kk = 0; kk < BK; kk++) {
            float4 a4 = *(const float4*)&Xs [kk][ty*4];
            float4 q4 = *(const float4*)&Bqs[kk][tx*4];
            float4 k4 = *(const float4*)&Bks[kk][tx*4];
            float4 v4 = *(const float4*)&Bvs[kk][tx*4];
            float a [4] = {a4.x, a4.y, a4.z, a4.w};
            float qb[4] = {q4.x, q4.y, q4.z, q4.w};
            float kb[4] = {k4.x, k4.y, k4.z, k4.w};
            float vb[4] = {v4.x, v4.y, v4.z, v4.w};
            #pragma unroll
            for (int i = 0; i < 4; i++)
                #pragma unroll
                for (int j = 0; j < 4; j++) {
                    aq[i][j] += a[i]*qb[j];
                    ak[i][j] += a[i]*kb[j];
                    av[i][j] += a[i]*vb[j];
                }
        }
        __syncthreads();
    }

    const size_t base = (((size_t)b*HH + h)*SS + m0) * DH;
    #pragma unroll
    for (int i = 0; i < 4; i++) {
        size_t ro = base + (size_t)(ty*4+i)*DH + tx*4;
        *(float4*)&g_Q[ro] = make_float4(aq[i][0], aq[i][1], aq[i][2], aq[i][3]);
        *(float4*)&g_K[ro] = make_float4(ak[i][0], ak[i][1], ak[i][2], ak[i][3]);
        *(float4*)&g_V[ro] = make_float4(av[i][0], av[i][1], av[i][2], av[i][3]);
    }
}

// ---------------------------------------------------------------------------
// Kernel 2: causal flash attention, one (b, h, 64-row q-tile) per block.
// Online softmax; O accumulator in registers (4x4 per thread).
// ---------------------------------------------------------------------------
#define TPAD 68                 // 64 + 4 pad (keeps float4 alignment)
#define TILE_F (64*TPAD)        // floats per 64x64 tile

__global__ __launch_bounds__(256, 2)
void attn_kernel(float* __restrict__ out) {
    extern __shared__ float sm[];
    float* Qs   = sm;                 // [e][i] transposed
    float* Ks   = sm + TILE_F;        // [e][j] transposed
    float* Vs   = sm + 2*TILE_F;      // [j][e]
    float* Ps   = sm + 3*TILE_F;      // [i][j]
    float* mrow = sm + 4*TILE_F;      // [64]
    float* lrow = mrow + 64;          // [64]
    float* arow = lrow + 64;          // [64]

    const int mt = gridDim.x - 1 - blockIdx.x;   // long blocks first
    const int h = blockIdx.y, b = blockIdx.z;
    const int tid = threadIdx.x;
    const int tx = tid & 15, ty = tid >> 4;
    const int m0 = mt * 64;
    const size_t bh = ((size_t)b*HH + h) * SS;
    const float scale = 0.125f;                  // 1/sqrt(64)

    // Load Q tile transposed: Qs[e][i]
    #pragma unroll
    for (int u = 0; u < 16; u++) {
        int idx = tid + u*256;        // 0..4095
        int r = idx >> 6, e = idx & 63;
        Qs[e*TPAD + r] = g_Q[(bh + m0 + r)*DH + e];
    }
    if (tid < 64) { mrow[tid] = -1e30f; lrow[tid] = 0.f; }

    float o[4][4] = {};
    __syncthreads();

    for (int kt = 0; kt <= mt; kt++) {
        // Load K (transposed) and V tiles
        #pragma unroll
        for (int u = 0; u < 16; u++) {
            int idx = tid + u*256;
            int r = idx >> 6, e = idx & 63;
            size_t g = (bh + kt*64 + r)*DH + e;
            Ks[e*TPAD + r] = g_K[g];
            Vs[r*TPAD + e] = g_V[g];
        }
        __syncthreads();

        // S = Q @ K^T
        float s[4][4] = {};
        #pragma unroll 8
        for (int e = 0; e < 64; e++) {
            float4 a4 = *(const float4*)&Qs[e*TPAD + ty*4];
            float4 b4 = *(const float4*)&Ks[e*TPAD + tx*4];
            float a[4] = {a4.x, a4.y, a4.z, a4.w};
            float bb[4] = {b4.x, b4.y, b4.z, b4.w};
            #pragma unroll
            for (int i = 0; i < 4; i++)
                #pragma unroll
                for (int j = 0; j < 4; j++)
                    s[i][j] += a[i]*bb[j];
        }

        // scale, causal mask, write to Ps
        #pragma unroll
        for (int i = 0; i < 4; i++) {
            int gr = m0 + ty*4 + i;
            #pragma unroll
            for (int j = 0; j < 4; j++) {
                int gc = kt*64 + tx*4 + j;
                float v = s[i][j] * scale;
                if (gc > gr) v = -1e30f;
                Ps[(ty*4+i)*TPAD + tx*4 + j] = v;
            }
        }
        __syncthreads();

        // Online softmax: 4 threads per row, 16 cols each
        {
            int r = tid >> 2, c0 = (tid & 3) * 16;
            float* prow = &Ps[r*TPAD + c0];
            float mx = -1e30f;
            #pragma unroll
            for (int c = 0; c < 16; c++) mx = fmaxf(mx, prow[c]);
            mx = fmaxf(mx, __shfl_xor_sync(0xffffffffu, mx, 1));
            mx = fmaxf(mx, __shfl_xor_sync(0xffffffffu, mx, 2));
            float mold = mrow[r];
            float mnew = fmaxf(mold, mx);
            float sum = 0.f;
            #pragma unroll
            for (int c = 0; c < 16; c++) {
                float p = __expf(prow[c] - mnew);
                prow[c] = p;
                sum += p;
            }
            sum += __shfl_xor_sync(0xffffffffu, sum, 1);
            sum += __shfl_xor_sync(0xffffffffu, sum, 2);
            float alpha = __expf(mold - mnew);
            if ((tid & 3) == 0) {
                mrow[r] = mnew;
                lrow[r] = lrow[r]*alpha + sum;
                arow[r] = alpha;
            }
        }
        __syncthreads();

        // Rescale O, then O += P @ V
        float al[4];
        #pragma unroll
        for (int i = 0; i < 4; i++) al[i] = arow[ty*4+i];
        #pragma unroll
        for (int i = 0; i < 4; i++)
            #pragma unroll
            for (int j = 0; j < 4; j++) o[i][j] *= al[i];

        #pragma unroll 4
        for (int j0 = 0; j0 < 64; j0 += 4) {
            float pi[4][4];
            #pragma unroll
            for (int i = 0; i < 4; i++) {
                float4 p4 = *(const float4*)&Ps[(ty*4+i)*TPAD + j0];
                pi[i][0]=p4.x; pi[i][1]=p4.y; pi[i][2]=p4.z; pi[i][3]=p4.w;
            }
            #pragma unroll
            for (int jj = 0; jj < 4; jj++) {
                float4 v4 = *(const float4*)&Vs[(j0+jj)*TPAD + tx*4];
                float vv[4] = {v4.x, v4.y, v4.z, v4.w};
                #pragma unroll
                for (int i = 0; i < 4; i++)
                    #pragma unroll
                    for (int e = 0; e < 4; e++)
                        o[i][e] += pi[i][jj]*vv[e];
            }
        }
        __syncthreads();   // before Ks/Vs/Ps are overwritten
    }

    // Epilogue: normalize and write [B, S, H*DH]
    #pragma unroll
    for (int i = 0; i < 4; i++) {
        int r = ty*4 + i;
        float inv = 1.f / lrow[r];
        float4 res = make_float4(o[i][0]*inv, o[i][1]*inv, o[i][2]*inv, o[i][3]*inv);
        *(float4*)&out[((size_t)b*SS + m0 + r)*(HH*DH) + h*DH + tx*4] = res;
    }
}

// ---------------------------------------------------------------------------
extern "C" void kernel_launch(void* const* d_in, const int* in_sizes, int n_in,
                              void* d_out, int out_size) {
    const float* x  = (const float*)d_in[0];
    const float* Wq = (const float*)d_in[1];
    const float* Wk = (const float*)d_in[2];
    const float* Wv = (const float*)d_in[3];
    float* out = (float*)d_out;

    dim3 grid(SS/64, HH, BB);

    qkv_proj_kernel<<<grid, 256>>>(x, Wq, Wk, Wv);

    const int smem_bytes = (4*TILE_F + 3*64) * (int)sizeof(float);  // ~70.4 KB
    static int attr_set = 0;
    // idempotent; safe every call (not a stream op, graph-capture compatible)
    cudaFuncSetAttribute(attn_kernel, cudaFuncAttributeMaxDynamicSharedMemorySize,
                         smem_bytes);
    (void)attr_set;
    attn_kernel<<<grid, 256, smem_bytes>>>(out);
}

// round 2
// speedup vs baseline: 1.7490x; 1.7490x over previous
#include <cuda_runtime.h>
#include <cstdint>

// Problem constants
#define BB   4
#define SS   1024
#define DIN  768
#define HH   12
#define DH   64

// Scratch for projected Q/K/V in [b,h,s,e] layout (device globals: no allocs allowed)
__device__ float g_Q[BB*HH*SS*DH];
__device__ float g_K[BB*HH*SS*DH];
__device__ float g_V[BB*HH*SS*DH];

// ---------------------------------------------------------------------------
// tf32 helpers
// ---------------------------------------------------------------------------
__device__ __forceinline__ uint32_t f2tf32(float f) {
    uint32_t r;
    asm("cvt.rna.tf32.f32 %0, %1;" : "=r"(r) : "f"(f));
    return r;
}

__device__ __forceinline__ void mma_tf32(float c[4],
                                         uint32_t a0, uint32_t a1, uint32_t a2, uint32_t a3,
                                         uint32_t b0, uint32_t b1) {
    asm volatile(
        "mma.sync.aligned.m16n8k8.row.col.f32.tf32.tf32.f32 "
        "{%0,%1,%2,%3}, {%4,%5,%6,%7}, {%8,%9}, {%0,%1,%2,%3};"
        : "+f"(c[0]), "+f"(c[1]), "+f"(c[2]), "+f"(c[3])
        : "r"(a0), "r"(a1), "r"(a2), "r"(a3), "r"(b0), "r"(b1));
}

// ---------------------------------------------------------------------------
// Kernel 1: fused QKV projection via tf32 tensor-core mma.
// grid (4096/128, 12) ; 512 threads (16 warps: 4 in M x 4 in N).
// Block tile: M=128 rows, N=64 cols per matrix, x3 matrices (Q,K,V).
// Warp tile:  m32 x n16 per matrix.
// ---------------------------------------------------------------------------
#define XSTR 36     // Xs row stride: A-frag bank = (t/4)*4 + t%4, conflict-free
#define WSTR 72     // Ws row stride: B-frag bank = (t%4)*8 + t/4, conflict-free

__global__ __launch_bounds__(512, 1)
void qkv_proj_kernel(const float* __restrict__ x,
                     const float* __restrict__ Wq,
                     const float* __restrict__ Wk,
                     const float* __restrict__ Wv) {
    __shared__ uint32_t Xs[128*XSTR];      // [row][k], tf32 bits
    __shared__ uint32_t Ws[3][32*WSTR];    // [mat][k][n], tf32 bits

    const int tid = threadIdx.x;
    const int wid = tid >> 5, lane = tid & 31;
    const int tg = lane >> 2, tig = lane & 3;    // groupID, threadID_in_group
    const int wm = wid >> 2, wn = wid & 3;       // warp coords: 4x4
    const int h = blockIdx.y;
    const int rowblk = blockIdx.x * 128;

    const float* xb = x + (size_t)rowblk * DIN;
    const float* wp[3] = { Wq + (size_t)h * DIN * DH,
                           Wk + (size_t)h * DIN * DH,
                           Wv + (size_t)h * DIN * DH };

    // accumulators: [mat][m-sub(2)][n-tile(2)][4]
    float acc[3][2][2][4];
    #pragma unroll
    for (int m = 0; m < 3; m++)
        #pragma unroll
        for (int i = 0; i < 2; i++)
            #pragma unroll
            for (int j = 0; j < 2; j++)
                #pragma unroll
                for (int r = 0; r < 4; r++) acc[m][i][j][r] = 0.f;

    // X load indexing: 1024 float4 per chunk, 2 per thread
    const int xr0 = tid >> 2;              // row for iter 0: tid/4? no -> see below
    // We use: idx = tid + it*512 ; row = idx>>3 ; c4 = idx&7
    // W load indexing: 512 float4 per matrix per chunk, 1 per thread
    const int wk_ = tid >> 4, wn4 = (tid & 15) * 4;

    float4 xv[2], wv[3];

    // prefetch chunk 0
    {
        #pragma unroll
        for (int it = 0; it < 2; it++) {
            int idx = tid + it*512, row = idx >> 3, c4 = (idx & 7) * 4;
            xv[it] = *(const float4*)&xb[(size_t)row*DIN + c4];
        }
        #pragma unroll
        for (int m = 0; m < 3; m++)
            wv[m] = *(const float4*)&wp[m][(size_t)wk_*DH + wn4];
    }

    for (int kc = 0; kc < DIN/32; kc++) {
        __syncthreads();   // previous iteration's consumers done
        // store staged chunk
        #pragma unroll
        for (int it = 0; it < 2; it++) {
            int idx = tid + it*512, row = idx >> 3, c4 = (idx & 7) * 4;
            uint32_t* p = &Xs[row*XSTR + c4];
            p[0] = f2tf32(xv[it].x); p[1] = f2tf32(xv[it].y);
            p[2] = f2tf32(xv[it].z); p[3] = f2tf32(xv[it].w);
        }
        #pragma unroll
        for (int m = 0; m < 3; m++) {
            uint32_t* p = &Ws[m][wk_*WSTR + wn4];
            p[0] = f2tf32(wv[m].x); p[1] = f2tf32(wv[m].y);
            p[2] = f2tf32(wv[m].z); p[3] = f2tf32(wv[m].w);
        }
        __syncthreads();

        // prefetch next chunk (overlaps with mma below)
        if (kc + 1 < DIN/32) {
            int k0n = (kc + 1) * 32;
            #pragma unroll
            for (int it = 0; it < 2; it++) {
                int idx = tid + it*512, row = idx >> 3, c4 = (idx & 7) * 4;
                xv[it] = *(const float4*)&xb[(size_t)row*DIN + k0n + c4];
            }
            #pragma unroll
            for (int m = 0; m < 3; m++)
                wv[m] = *(const float4*)&wp[m][(size_t)(k0n + wk_)*DH + wn4];
        }

        // compute: 4 k8-steps
        #pragma unroll
        for (int kk = 0; kk < 4; kk++) {
            const int k0 = kk * 8;
            // A fragments for the two m16 subtiles
            uint32_t a[2][4];
            #pragma unroll
            for (int ms = 0; ms < 2; ms++) {
                int r0 = wm*32 + ms*16 + tg;
                a[ms][0] = Xs[(r0    )*XSTR + k0 + tig    ];
                a[ms][1] = Xs[(r0 + 8)*XSTR + k0 + tig    ];
                a[ms][2] = Xs[(r0    )*XSTR + k0 + tig + 4];
                a[ms][3] = Xs[(r0 + 8)*XSTR + k0 + tig + 4];
            }
            #pragma unroll
            for (int m = 0; m < 3; m++) {
                #pragma unroll
                for (int j = 0; j < 2; j++) {
                    int n0 = wn*16 + j*8 + tg;
                    uint32_t b0 = Ws[m][(k0 + tig    )*WSTR + n0];
                    uint32_t b1 = Ws[m][(k0 + tig + 4)*WSTR + n0];
                    #pragma unroll
                    for (int ms = 0; ms < 2; ms++)
                        mma_tf32(acc[m][ms][j], a[ms][0], a[ms][1], a[ms][2], a[ms][3], b0, b1);
                }
            }
        }
    }

    // Epilogue: write to g_Q/g_K/g_V [b][h][s][e]
    const int b = rowblk >> 10;                 // 128-row blocks never cross batch
    const int s0 = rowblk & 1023;
    float* gp[3] = { g_Q, g_K, g_V };
    const size_t base = (((size_t)b*HH + h)*SS);
    #pragma unroll
    for (int m = 0; m < 3; m++) {
        #pragma unroll
        for (int ms = 0; ms < 2; ms++) {
            int r0 = s0 + wm*32 + ms*16 + tg;
            #pragma unroll
            for (int j = 0; j < 2; j++) {
                int c0 = wn*16 + j*8 + tig*2;
                float* g = gp[m];
                *(float2*)&g[(base + r0    )*DH + c0] = make_float2(acc[m][ms][j][0], acc[m][ms][j][1]);
                *(float2*)&g[(base + r0 + 8)*DH + c0] = make_float2(acc[m][ms][j][2], acc[m][ms][j][3]);
            }
        }
    }
}

// ---------------------------------------------------------------------------
// Kernel 2: causal flash attention (unchanged from round 1).
// ---------------------------------------------------------------------------
#define TPAD 68
#define TILE_F (64*TPAD)

__global__ __launch_bounds__(256, 2)
void attn_kernel(float* __restrict__ out) {
    extern __shared__ float sm[];
    float* Qs   = sm;
    float* Ks   = sm + TILE_F;
    float* Vs   = sm + 2*TILE_F;
    float* Ps   = sm + 3*TILE_F;
    float* mrow = sm + 4*TILE_F;
    float* lrow = mrow + 64;
    float* arow = lrow + 64;

    const int mt = gridDim.x - 1 - blockIdx.x;
    const int h = blockIdx.y, b = blockIdx.z;
    const int tid = threadIdx.x;
    const int tx = tid & 15, ty = tid >> 4;
    const int m0 = mt * 64;
    const size_t bh = ((size_t)b*HH + h) * SS;
    const float scale = 0.125f;

    #pragma unroll
    for (int u = 0; u < 16; u++) {
        int idx = tid + u*256;
        int r = idx >> 6, e = idx & 63;
        Qs[e*TPAD + r] = g_Q[(bh + m0 + r)*DH + e];
    }
    if (tid < 64) { mrow[tid] = -1e30f; lrow[tid] = 0.f; }

    float o[4][4] = {};
    __syncthreads();

    for (int kt = 0; kt <= mt; kt++) {
        #pragma unroll
        for (int u = 0; u < 16; u++) {
            int idx = tid + u*256;
            int r = idx >> 6, e = idx & 63;
            size_t g = (bh + kt*64 + r)*DH + e;
            Ks[e*TPAD + r] = g_K[g];
            Vs[r*TPAD + e] = g_V[g];
        }
        __syncthreads();

        float s[4][4] = {};
        #pragma unroll 8
        for (int e = 0; e < 64; e++) {
            float4 a4 = *(const float4*)&Qs[e*TPAD + ty*4];
            float4 b4 = *(const float4*)&Ks[e*TPAD + tx*4];
            float a[4] = {a4.x, a4.y, a4.z, a4.w};
            float bb[4] = {b4.x, b4.y, b4.z, b4.w};
            #pragma unroll
            for (int i = 0; i < 4; i++)
                #pragma unroll
                for (int j = 0; j < 4; j++)
                    s[i][j] += a[i]*bb[j];
        }

        #pragma unroll
        for (int i = 0; i < 4; i++) {
            int gr = m0 + ty*4 + i;
            #pragma unroll
            for (int j = 0; j < 4; j++) {
                int gc = kt*64 + tx*4 + j;
                float v = s[i][j] * scale;
                if (gc > gr) v = -1e30f;
                Ps[(ty*4+i)*TPAD + tx*4 + j] = v;
            }
        }
        __syncthreads();

        {
            int r = tid >> 2, c0 = (tid & 3) * 16;
            float* prow = &Ps[r*TPAD + c0];
            float mx = -1e30f;
            #pragma unroll
            for (int c = 0; c < 16; c++) mx = fmaxf(mx, prow[c]);
            mx = fmaxf(mx, __shfl_xor_sync(0xffffffffu, mx, 1));
            mx = fmaxf(mx, __shfl_xor_sync(0xffffffffu, mx, 2));
            float mold = mrow[r];
            float mnew = fmaxf(mold, mx);
            float sum = 0.f;
            #pragma unroll
            for (int c = 0; c < 16; c++) {
                float p = __expf(prow[c] - mnew);
                prow[c] = p;
                sum += p;
            }
            sum += __shfl_xor_sync(0xffffffffu, sum, 1);
            sum += __shfl_xor_sync(0xffffffffu, sum, 2);
            float alpha = __expf(mold - mnew);
            if ((tid & 3) == 0) {
                mrow[r] = mnew;
                lrow[r] = lrow[r]*alpha + sum;
                arow[r] = alpha;
            }
        }
        __syncthreads();

        float al[4];
        #pragma unroll
        for (int i = 0; i < 4; i++) al[i] = arow[ty*4+i];
        #pragma unroll
        for (int i = 0; i < 4; i++)
            #pragma unroll
            for (int j = 0; j < 4; j++) o[i][j] *= al[i];

        #pragma unroll 4
        for (int j0 = 0; j0 < 64; j0 += 4) {
            float pi[4][4];
            #pragma unroll
            for (int i = 0; i < 4; i++) {
                float4 p4 = *(const float4*)&Ps[(ty*4+i)*TPAD + j0];
                pi[i][0]=p4.x; pi[i][1]=p4.y; pi[i][2]=p4.z; pi[i][3]=p4.w;
            }
            #pragma unroll
            for (int jj = 0; jj < 4; jj++) {
                float4 v4 = *(const float4*)&Vs[(j0+jj)*TPAD + tx*4];
                float vv[4] = {v4.x, v4.y, v4.z, v4.w};
                #pragma unroll
                for (int i = 0; i < 4; i++)
                    #pragma unroll
                    for (int e = 0; e < 4; e++)
                        o[i][e] += pi[i][jj]*vv[e];
            }
        }
        __syncthreads();
    }

    #pragma unroll
    for (int i = 0; i < 4; i++) {
        int r = ty*4 + i;
        float inv = 1.f / lrow[r];
        float4 res = make_float4(o[i][0]*inv, o[i][1]*inv, o[i][2]*inv, o[i][3]*inv);
        *(float4*)&out[((size_t)b*SS + m0 + r)*(HH*DH) + h*DH + tx*4] = res;
    }
}

// ---------------------------------------------------------------------------
extern "C" void kernel_launch(void* const* d_in, const int* in_sizes, int n_in,
                              void* d_out, int out_size) {
    const float* x  = (const float*)d_in[0];
    const float* Wq = (const float*)d_in[1];
    const float* Wk = (const float*)d_in[2];
    const float* Wv = (const float*)d_in[3];
    float* out = (float*)d_out;

    qkv_proj_kernel<<<dim3((BB*SS)/128, HH), 512>>>(x, Wq, Wk, Wv);

    const int smem_bytes = (4*TILE_F + 3*64) * (int)sizeof(float);
    cudaFuncSetAttribute(attn_kernel, cudaFuncAttributeMaxDynamicSharedMemorySize,
                         smem_bytes);
    attn_kernel<<<dim3(SS/64, HH, BB), 256, smem_bytes>>>(out);
}

// round 3
// speedup vs baseline: 2.6975x; 1.5422x over previous
#include <cuda_runtime.h>
#include <cstdint>

// Problem constants
#define BB   4
#define SS   1024
#define DIN  768
#define HH   12
#define DH   64

// Scratch (device globals: no allocs allowed)
__device__ float g_Q [BB*HH*SS*DH];   // [b,h,s,e]
__device__ float g_K [BB*HH*SS*DH];   // [b,h,s,e]
__device__ float g_Vt[BB*HH*DH*SS];   // [b,h,e,s]  (transposed!)

// ---------------------------------------------------------------------------
// tf32 helpers
// ---------------------------------------------------------------------------
__device__ __forceinline__ uint32_t f2tf32(float f) {
    uint32_t r;
    asm("cvt.rna.tf32.f32 %0, %1;" : "=r"(r) : "f"(f));
    return r;
}

__device__ __forceinline__ void mma_tf32(float c[4],
                                         uint32_t a0, uint32_t a1, uint32_t a2, uint32_t a3,
                                         uint32_t b0, uint32_t b1) {
    asm volatile(
        "mma.sync.aligned.m16n8k8.row.col.f32.tf32.tf32.f32 "
        "{%0,%1,%2,%3}, {%4,%5,%6,%7}, {%8,%9}, {%0,%1,%2,%3};"
        : "+f"(c[0]), "+f"(c[1]), "+f"(c[2]), "+f"(c[3])
        : "r"(a0), "r"(a1), "r"(a2), "r"(a3), "r"(b0), "r"(b1));
}

// ---------------------------------------------------------------------------
// Kernel 1: fused QKV projection via tf32 mma (unchanged except V epilogue
// now writes g_Vt transposed).
// grid (4096/128, 12); 512 threads (16 warps: 4 in M x 4 in N).
// ---------------------------------------------------------------------------
#define XSTR 36
#define WSTR 72

__global__ __launch_bounds__(512, 1)
void qkv_proj_kernel(const float* __restrict__ x,
                     const float* __restrict__ Wq,
                     const float* __restrict__ Wk,
                     const float* __restrict__ Wv) {
    __shared__ uint32_t Xs[128*XSTR];
    __shared__ uint32_t Ws[3][32*WSTR];

    const int tid = threadIdx.x;
    const int wid = tid >> 5, lane = tid & 31;
    const int tg = lane >> 2, tig = lane & 3;
    const int wm = wid >> 2, wn = wid & 3;
    const int h = blockIdx.y;
    const int rowblk = blockIdx.x * 128;

    const float* xb = x + (size_t)rowblk * DIN;
    const float* wp[3] = { Wq + (size_t)h * DIN * DH,
                           Wk + (size_t)h * DIN * DH,
                           Wv + (size_t)h * DIN * DH };

    float acc[3][2][2][4];
    #pragma unroll
    for (int m = 0; m < 3; m++)
        #pragma unroll
        for (int i = 0; i < 2; i++)
            #pragma unroll
            for (int j = 0; j < 2; j++)
                #pragma unroll
                for (int r = 0; r < 4; r++) acc[m][i][j][r] = 0.f;

    const int wk_ = tid >> 4, wn4 = (tid & 15) * 4;

    float4 xv[2], wv[3];
    {
        #pragma unroll
        for (int it = 0; it < 2; it++) {
            int idx = tid + it*512, row = idx >> 3, c4 = (idx & 7) * 4;
            xv[it] = *(const float4*)&xb[(size_t)row*DIN + c4];
        }
        #pragma unroll
        for (int m = 0; m < 3; m++)
            wv[m] = *(const float4*)&wp[m][(size_t)wk_*DH + wn4];
    }

    for (int kc = 0; kc < DIN/32; kc++) {
        __syncthreads();
        #pragma unroll
        for (int it = 0; it < 2; it++) {
            int idx = tid + it*512, row = idx >> 3, c4 = (idx & 7) * 4;
            uint32_t* p = &Xs[row*XSTR + c4];
            p[0] = f2tf32(xv[it].x); p[1] = f2tf32(xv[it].y);
            p[2] = f2tf32(xv[it].z); p[3] = f2tf32(xv[it].w);
        }
        #pragma unroll
        for (int m = 0; m < 3; m++) {
            uint32_t* p = &Ws[m][wk_*WSTR + wn4];
            p[0] = f2tf32(wv[m].x); p[1] = f2tf32(wv[m].y);
            p[2] = f2tf32(wv[m].z); p[3] = f2tf32(wv[m].w);
        }
        __syncthreads();

        if (kc + 1 < DIN/32) {
            int k0n = (kc + 1) * 32;
            #pragma unroll
            for (int it = 0; it < 2; it++) {
                int idx = tid + it*512, row = idx >> 3, c4 = (idx & 7) * 4;
                xv[it] = *(const float4*)&xb[(size_t)row*DIN + k0n + c4];
            }
            #pragma unroll
            for (int m = 0; m < 3; m++)
                wv[m] = *(const float4*)&wp[m][(size_t)(k0n + wk_)*DH + wn4];
        }

        #pragma unroll
        for (int kk = 0; kk < 4; kk++) {
            const int k0 = kk * 8;
            uint32_t a[2][4];
            #pragma unroll
            for (int ms = 0; ms < 2; ms++) {
                int r0 = wm*32 + ms*16 + tg;
                a[ms][0] = Xs[(r0    )*XSTR + k0 + tig    ];
                a[ms][1] = Xs[(r0 + 8)*XSTR + k0 + tig    ];
                a[ms][2] = Xs[(r0    )*XSTR + k0 + tig + 4];
                a[ms][3] = Xs[(r0 + 8)*XSTR + k0 + tig + 4];
            }
            #pragma unroll
            for (int m = 0; m < 3; m++) {
                #pragma unroll
                for (int j = 0; j < 2; j++) {
                    int n0 = wn*16 + j*8 + tg;
                    uint32_t b0 = Ws[m][(k0 + tig    )*WSTR + n0];
                    uint32_t b1 = Ws[m][(k0 + tig + 4)*WSTR + n0];
                    #pragma unroll
                    for (int ms = 0; ms < 2; ms++)
                        mma_tf32(acc[m][ms][j], a[ms][0], a[ms][1], a[ms][2], a[ms][3], b0, b1);
                }
            }
        }
    }

    // Epilogue
    const int b = rowblk >> 10;
    const int s0 = rowblk & 1023;
    const size_t base = (((size_t)b*HH + h)*SS);
    // Q, K: [b,h,s,e]
    float* gp[2] = { g_Q, g_K };
    #pragma unroll
    for (int m = 0; m < 2; m++) {
        #pragma unroll
        for (int ms = 0; ms < 2; ms++) {
            int r0 = s0 + wm*32 + ms*16 + tg;
            #pragma unroll
            for (int j = 0; j < 2; j++) {
                int c0 = wn*16 + j*8 + tig*2;
                float* g = gp[m];
                *(float2*)&g[(base + r0    )*DH + c0] = make_float2(acc[m][ms][j][0], acc[m][ms][j][1]);
                *(float2*)&g[(base + r0 + 8)*DH + c0] = make_float2(acc[m][ms][j][2], acc[m][ms][j][3]);
            }
        }
    }
    // V: transposed [b,h,e,s]
    const size_t vbase = ((size_t)b*HH + h) * DH;
    #pragma unroll
    for (int ms = 0; ms < 2; ms++) {
        int r0 = s0 + wm*32 + ms*16 + tg;
        #pragma unroll
        for (int j = 0; j < 2; j++) {
            int c0 = wn*16 + j*8 + tig*2;
            g_Vt[(vbase + c0    )*SS + r0    ] = acc[2][ms][j][0];
            g_Vt[(vbase + c0 + 1)*SS + r0    ] = acc[2][ms][j][1];
            g_Vt[(vbase + c0    )*SS + r0 + 8] = acc[2][ms][j][2];
            g_Vt[(vbase + c0 + 1)*SS + r0 + 8] = acc[2][ms][j][3];
        }
    }
}

// ---------------------------------------------------------------------------
// Kernel 2: tensor-core causal flash attention.
// grid (16, 12, 4); 128 threads (4 warps, warp = 16 q-rows).
// QK^T in 3xTF32 (near-fp32 scores), PV in tf32. Softmax stats in registers.
// ---------------------------------------------------------------------------
#define PST 68    // tile row stride (words): frag LDS bank = 4*tg + tig, conflict-free

__global__ __launch_bounds__(128, 2)
void attn_kernel(float* __restrict__ out) {
    extern __shared__ uint32_t smu[];
    uint32_t* Kb  = smu;               // [n][k]  tf32 big
    uint32_t* Ksm = smu + 64*PST;      // [n][k]  tf32 small
    uint32_t* Vs  = smu + 2*64*PST;    // [e][n]  tf32
    uint32_t* Ps  = smu + 3*64*PST;    // [m][n]  tf32

    const int mt = gridDim.x - 1 - blockIdx.x;   // heavy blocks first
    const int h = blockIdx.y, b = blockIdx.z;
    const int tid = threadIdx.x, wid = tid >> 5, lane = tid & 31;
    const int tg = lane >> 2, tig = lane & 3;
    const int m0 = mt * 64;
    const size_t bh = ((size_t)b*HH + h) * SS;
    const float* gq  = g_Q + bh*DH;
    const float* gk  = g_K + bh*DH;
    const float* gvt = g_Vt + ((size_t)b*HH + h) * DH * SS;

    // Q fragments (resident whole kernel): big + small tf32
    uint32_t qb[8][4], qs[8][4];
    {
        const int r0 = m0 + wid*16 + tg;
        #pragma unroll
        for (int k = 0; k < 8; k++) {
            float f[4];
            f[0] = gq[(size_t)(r0    )*DH + k*8 + tig    ];
            f[1] = gq[(size_t)(r0 + 8)*DH + k*8 + tig    ];
            f[2] = gq[(size_t)(r0    )*DH + k*8 + tig + 4];
            f[3] = gq[(size_t)(r0 + 8)*DH + k*8 + tig + 4];
            #pragma unroll
            for (int i = 0; i < 4; i++) {
                qb[k][i] = f2tf32(f[i]);
                qs[k][i] = f2tf32(f[i] - __uint_as_float(qb[k][i]));
            }
        }
    }

    float o[8][4];
    #pragma unroll
    for (int j = 0; j < 8; j++)
        #pragma unroll
        for (int i = 0; i < 4; i++) o[j][i] = 0.f;
    float mrow[2] = {-1e30f, -1e30f};
    float lrow[2] = {0.f, 0.f};

    for (int kt = 0; kt <= mt; kt++) {
        __syncthreads();   // previous tile consumers done

        // ---- load K tile (big+small) ----
        {
            float4 t[8];
            #pragma unroll
            for (int u = 0; u < 8; u++) {
                int idx = tid + u*128, r = idx >> 4, c4 = (idx & 15) * 4;
                t[u] = *(const float4*)&gk[(size_t)(kt*64 + r)*DH + c4];
            }
            #pragma unroll
            for (int u = 0; u < 8; u++) {
                int idx = tid + u*128, r = idx >> 4, c4 = (idx & 15) * 4;
                uint32_t b0 = f2tf32(t[u].x), b1 = f2tf32(t[u].y);
                uint32_t b2 = f2tf32(t[u].z), b3 = f2tf32(t[u].w);
                *(uint4*)&Kb[r*PST + c4] = make_uint4(b0, b1, b2, b3);
                uint32_t s0 = f2tf32(t[u].x - __uint_as_float(b0));
                uint32_t s1 = f2tf32(t[u].y - __uint_as_float(b1));
                uint32_t s2 = f2tf32(t[u].z - __uint_as_float(b2));
                uint32_t s3 = f2tf32(t[u].w - __uint_as_float(b3));
                *(uint4*)&Ksm[r*PST + c4] = make_uint4(s0, s1, s2, s3);
            }
        }
        // ---- load V tile (already transposed in gmem) ----
        {
            float4 t[8];
            #pragma unroll
            for (int u = 0; u < 8; u++) {
                int idx = tid + u*128, e = idx >> 4, n4 = (idx & 15) * 4;
                t[u] = *(const float4*)&gvt[(size_t)e*SS + kt*64 + n4];
            }
            #pragma unroll
            for (int u = 0; u < 8; u++) {
                int idx = tid + u*128, e = idx >> 4, n4 = (idx & 15) * 4;
                *(uint4*)&Vs[e*PST + n4] = make_uint4(f2tf32(t[u].x), f2tf32(t[u].y),
                                                      f2tf32(t[u].z), f2tf32(t[u].w));
            }
        }
        __syncthreads();

        // ---- S = Q K^T  (3xTF32) ----
        float c[8][4];
        #pragma unroll
        for (int j = 0; j < 8; j++)
            #pragma unroll
            for (int i = 0; i < 4; i++) c[j][i] = 0.f;

        #pragma unroll
        for (int k = 0; k < 8; k++) {
            #pragma unroll
            for (int j = 0; j < 8; j++) {
                const int nr = j*8 + tg;
                uint32_t b0 = Kb [nr*PST + k*8 + tig];
                uint32_t b1 = Kb [nr*PST + k*8 + tig + 4];
                uint32_t s0 = Ksm[nr*PST + k*8 + tig];
                uint32_t s1 = Ksm[nr*PST + k*8 + tig + 4];
                mma_tf32(c[j], qb[k][0], qb[k][1], qb[k][2], qb[k][3], b0, b1);
                mma_tf32(c[j], qs[k][0], qs[k][1], qs[k][2], qs[k][3], b0, b1);
                mma_tf32(c[j], qb[k][0], qb[k][1], qb[k][2], qb[k][3], s0, s1);
            }
        }

        // ---- scale + causal mask ----
        const float sc = 0.125f;
        #pragma unroll
        for (int j = 0; j < 8; j++)
            #pragma unroll
            for (int i = 0; i < 4; i++) c[j][i] *= sc;

        if (kt == mt) {
            const int rl0 = wid*16 + tg, rl1 = rl0 + 8;
            #pragma unroll
            for (int j = 0; j < 8; j++) {
                int c0 = j*8 + 2*tig, c1 = c0 + 1;
                if (c0 > rl0) c[j][0] = -1e30f;
                if (c1 > rl0) c[j][1] = -1e30f;
                if (c0 > rl1) c[j][2] = -1e30f;
                if (c1 > rl1) c[j][3] = -1e30f;
            }
        }

        // ---- online softmax (register stats, 4-lane shuffles) ----
        float alpha[2];
        #pragma unroll
        for (int h2 = 0; h2 < 2; h2++) {
            float mx = -1e30f;
            #pragma unroll
            for (int j = 0; j < 8; j++) {
                mx = fmaxf(mx, c[j][h2*2]);
                mx = fmaxf(mx, c[j][h2*2 + 1]);
            }
            mx = fmaxf(mx, __shfl_xor_sync(0xffffffffu, mx, 1));
            mx = fmaxf(mx, __shfl_xor_sync(0xffffffffu, mx, 2));
            float mnew = fmaxf(mrow[h2], mx);
            float sum = 0.f;
            #pragma unroll
            for (int j = 0; j < 8; j++) {
                float p0 = __expf(c[j][h2*2]     - mnew);
                float p1 = __expf(c[j][h2*2 + 1] - mnew);
                c[j][h2*2]     = p0;
                c[j][h2*2 + 1] = p1;
                sum += p0 + p1;
            }
            sum += __shfl_xor_sync(0xffffffffu, sum, 1);
            sum += __shfl_xor_sync(0xffffffffu, sum, 2);
            alpha[h2] = __expf(mrow[h2] - mnew);
            mrow[h2] = mnew;
            lrow[h2] = lrow[h2]*alpha[h2] + sum;
        }

        // ---- write P (tf32) + rescale O ----
        {
            const int rb0 = (wid*16 + tg)*PST, rb1 = rb0 + 8*PST;
            #pragma unroll
            for (int j = 0; j < 8; j++) {
                int cc = j*8 + 2*tig;
                *(uint2*)&Ps[rb0 + cc] = make_uint2(f2tf32(c[j][0]), f2tf32(c[j][1]));
                *(uint2*)&Ps[rb1 + cc] = make_uint2(f2tf32(c[j][2]), f2tf32(c[j][3]));
            }
        }
        #pragma unroll
        for (int j = 0; j < 8; j++) {
            o[j][0] *= alpha[0]; o[j][1] *= alpha[0];
            o[j][2] *= alpha[1]; o[j][3] *= alpha[1];
        }
        __syncwarp();

        // ---- O += P V ----
        #pragma unroll
        for (int k = 0; k < 8; k++) {       // k over key dim
            uint32_t p0 = Ps[(wid*16 + tg    )*PST + k*8 + tig];
            uint32_t p1 = Ps[(wid*16 + tg + 8)*PST + k*8 + tig];
            uint32_t p2 = Ps[(wid*16 + tg    )*PST + k*8 + tig + 4];
            uint32_t p3 = Ps[(wid*16 + tg + 8)*PST + k*8 + tig + 4];
            #pragma unroll
            for (int j = 0; j < 8; j++) {   // j over dh tiles
                uint32_t v0 = Vs[(j*8 + tg)*PST + k*8 + tig];
                uint32_t v1 = Vs[(j*8 + tg)*PST + k*8 + tig + 4];
                mma_tf32(o[j], p0, p1, p2, p3, v0, v1);
            }
        }
    }

    // ---- epilogue: normalize + write [B,S,H*DH] ----
    const float inv0 = 1.f / lrow[0], inv1 = 1.f / lrow[1];
    const int r0 = m0 + wid*16 + tg;
    #pragma unroll
    for (int j = 0; j < 8; j++) {
        int col = h*DH + j*8 + 2*tig;
        *(float2*)&out[((size_t)b*SS + r0    )*(HH*DH) + col] =
            make_float2(o[j][0]*inv0, o[j][1]*inv0);
        *(float2*)&out[((size_t)b*SS + r0 + 8)*(HH*DH) + col] =
            make_float2(o[j][2]*inv1, o[j][3]*inv1);
    }
}

// ---------------------------------------------------------------------------
extern "C" void kernel_launch(void* const* d_in, const int* in_sizes, int n_in,
                              void* d_out, int out_size) {
    const float* x  = (const float*)d_in[0];
    const float* Wq = (const float*)d_in[1];
    const float* Wk = (const float*)d_in[2];
    const float* Wv = (const float*)d_in[3];
    float* out = (float*)d_out;

    qkv_proj_kernel<<<dim3((BB*SS)/128, HH), 512>>>(x, Wq, Wk, Wv);

    const int smem_bytes = 4 * 64 * PST * (int)sizeof(uint32_t);   // 69,632 B
    cudaFuncSetAttribute(attn_kernel, cudaFuncAttributeMaxDynamicSharedMemorySize,
                         smem_bytes);
    attn_kernel<<<dim3(SS/64, HH, BB), 128, smem_bytes>>>(out);
}